// round 3
// baseline (speedup 1.0000x reference)
#include <cuda_runtime.h>
#include <math.h>

#define BB    256
#define NN    32
#define FF    40
#define HH    100
#define MM    100
#define EFN   4
#define OUTD  128
#define H3    300
#define KMAX  8
#define NODES (BB*NN)   // 8192

typedef unsigned long long ull;

// ---------------- device scratch (transposed layouts: [feature][node]) ----
__device__ __align__(16) float g_hA[HH*NODES];
__device__ __align__(16) float g_hB[HH*NODES];
__device__ __align__(16) float g_msgT[MM*NODES];
__device__ __align__(16) ull   g_WmP [EFN*HH*MM];  // [f][k][m], packed {w,w}
__device__ __align__(16) ull   g_WihP[MM*H3];      // [k][r], packed
__device__ __align__(16) ull   g_WhhP[HH*H3];      // [k][r], packed
__device__ int   g_nbr[NODES*KMAX];
__device__ int   g_typ[NODES*KMAX];
__device__ float g_wgt[NODES*KMAX];
__device__ int   g_cnt[NODES];

__device__ __forceinline__ float sigmf(float x) { return 1.0f / (1.0f + expf(-x)); }
__device__ __forceinline__ ull packdup(float w) {
    ull r; asm("mov.b64 %0,{%1,%1};" : "=l"(r) : "f"(w)); return r;
}
__device__ __forceinline__ ull pack2(float lo, float hi) {
    ull r; asm("mov.b64 %0,{%1,%2};" : "=l"(r) : "f"(lo), "f"(hi)); return r;
}
__device__ __forceinline__ void unpack2(ull v, float& lo, float& hi) {
    asm("mov.b64 {%0,%1},%2;" : "=f"(lo), "=f"(hi) : "l"(v));
}
__device__ __forceinline__ void fma2(ull& d, ull a, ull b) {
    asm("fma.rn.f32x2 %0, %1, %2, %0;" : "+l"(d) : "l"(a), "l"(b));
}

// ---------------- prep: pack weights ----------------
__global__ void prep_weights(const float* __restrict__ W_msg,
                             const float* __restrict__ W_ih,
                             const float* __restrict__ W_hh) {
    int gid = blockIdx.x * blockDim.x + threadIdx.x;
    const int NWT = EFN*HH*MM;            // 40000
    const int NWI = MM*H3;                // 30000
    if (gid < NWT) {
        int f = gid / (HH*MM);
        int rem = gid % (HH*MM);
        int k = rem / MM;
        int m = rem % MM;
        g_WmP[gid] = packdup(W_msg[(m*HH + k)*EFN + f]);
    } else if (gid < NWT + NWI) {
        int t = gid - NWT;
        int k = t / H3, r = t % H3;
        g_WihP[t] = packdup(W_ih[r*MM + k]);
    } else if (gid < NWT + NWI + HH*H3) {
        int t = gid - NWT - NWI;
        int k = t / H3, r = t % H3;
        g_WhhP[t] = packdup(W_hh[r*HH + k]);
    }
}

// ---------------- prep: compact edge lists (warp per node) ----------------
__global__ void prep_edges(const float* __restrict__ edges) {
    int warp = (blockIdx.x * blockDim.x + threadIdx.x) >> 5;
    int lane = threadIdx.x & 31;
    if (warp >= NODES) return;
    int p = warp;
    float4 v = ((const float4*)edges)[(size_t)p * NN + lane];
    float vv[4] = {v.x, v.y, v.z, v.w};
    int nl = (vv[0]!=0.f) + (vv[1]!=0.f) + (vv[2]!=0.f) + (vv[3]!=0.f);
    int inc = nl;
    #pragma unroll
    for (int off = 1; off < 32; off <<= 1) {
        int t = __shfl_up_sync(0xFFFFFFFFu, inc, off);
        if (lane >= off) inc += t;
    }
    int excl = inc - nl;
    int total = __shfl_sync(0xFFFFFFFFu, inc, 31);
    int c = excl;
    #pragma unroll
    for (int f = 0; f < EFN; f++) {
        if (vv[f] != 0.f && c < KMAX) {
            g_nbr[p*KMAX + c] = lane;
            g_typ[p*KMAX + c] = f;
            g_wgt[p*KMAX + c] = vv[f];
            c++;
        }
    }
    if (lane == 0) g_cnt[p] = (total < KMAX) ? total : KMAX;
}

// ---------------- init hidden (transposed [h][p]) ----------------
__global__ void init_hidden(const float* __restrict__ nodes) {
    int gid = blockIdx.x * blockDim.x + threadIdx.x;
    if (gid >= NODES*HH) return;
    int p = gid % NODES;
    int h = gid / NODES;
    g_hA[gid] = (h < FF) ? nodes[p*FF + h] : 0.0f;
}

// ---------------- messages: dense per-type transform + gather -------------
// grid = BB, block = 416 (400 active). hin layout [h][NODES].
__global__ __launch_bounds__(416, 2) void msg_kernel(const float* __restrict__ hin) {
    __shared__ __align__(16) float sh_hT[HH][NN];       // 12.8KB
    __shared__ __align__(16) ull   sh_T[EFN*MM*(NN/2)]; // [f][m][16 pairs] 51.2KB

    const int b   = blockIdx.x;
    const int tid = threadIdx.x;
    const int p0  = b * NN;

    // A: load batch hidden, coalesced
    for (int idx = tid; idx < HH*(NN/4); idx += 416) {   // 800 float4
        int k = idx >> 3, q = idx & 7;
        ((float4*)&sh_hT[k][0])[q] = ((const float4*)(hin + (size_t)k*NODES + p0))[q];
    }
    __syncthreads();

    // B: T[f][m][n] = sum_k W_f[k][m] * h_n[k], 4m x 8n register tile (f32x2)
    if (tid < 400) {
        const int wq = tid >> 2, ng = tid & 3;
        const int f = wq / 25, mq = wq % 25;
        ull acc[4][4];
        #pragma unroll
        for (int i = 0; i < 4; i++)
            #pragma unroll
            for (int j = 0; j < 4; j++) acc[i][j] = 0ull;
        for (int k = 0; k < HH; k++) {
            const ulonglong2* Wp = (const ulonglong2*)(g_WmP + (size_t)(f*HH + k)*MM);
            ulonglong2 wA = Wp[mq*2], wB = Wp[mq*2 + 1];
            const ulonglong2* hp = (const ulonglong2*)&sh_hT[k][ng*8];
            ulonglong2 h0 = hp[0], h1 = hp[1];
            fma2(acc[0][0], wA.x, h0.x); fma2(acc[0][1], wA.x, h0.y);
            fma2(acc[0][2], wA.x, h1.x); fma2(acc[0][3], wA.x, h1.y);
            fma2(acc[1][0], wA.y, h0.x); fma2(acc[1][1], wA.y, h0.y);
            fma2(acc[1][2], wA.y, h1.x); fma2(acc[1][3], wA.y, h1.y);
            fma2(acc[2][0], wB.x, h0.x); fma2(acc[2][1], wB.x, h0.y);
            fma2(acc[2][2], wB.x, h1.x); fma2(acc[2][3], wB.x, h1.y);
            fma2(acc[3][0], wB.y, h0.x); fma2(acc[3][1], wB.y, h0.y);
            fma2(acc[3][2], wB.y, h1.x); fma2(acc[3][3], wB.y, h1.y);
        }
        #pragma unroll
        for (int mi = 0; mi < 4; mi++) {
            ulonglong2* dst = (ulonglong2*)&sh_T[(size_t)(f*MM + mq*4 + mi)*16 + ng*4];
            dst[0] = make_ulonglong2(acc[mi][0], acc[mi][1]);
            dst[1] = make_ulonglong2(acc[mi][2], acc[mi][3]);
        }
    }
    __syncthreads();

    // C: gather msg[n][m] = sum_e w_e * T[f_e][m][g_e]; write transposed
    if (tid < 400) {
        const int m = tid >> 2, ng = tid & 3, n0 = ng*8;
        float res[8];
        #pragma unroll
        for (int j = 0; j < 8; j++) {
            int p = p0 + n0 + j;
            int c = g_cnt[p];
            float s = 0.f;
            for (int e = 0; e < c; e++) {
                int g = g_nbr[p*KMAX + e];
                int f = g_typ[p*KMAX + e];
                float w = g_wgt[p*KMAX + e];
                float lo, hi;
                unpack2(sh_T[(size_t)(f*MM + m)*16 + (g >> 1)], lo, hi);
                s += w * ((g & 1) ? hi : lo);
            }
            res[j] = s;
        }
        float4* out = (float4*)(g_msgT + (size_t)m*NODES + p0 + n0);
        out[0] = make_float4(res[0], res[1], res[2], res[3]);
        out[1] = make_float4(res[4], res[5], res[6], res[7]);
    }
}

// ---------------- GRU: 16 nodes/block, thread = (h, node-half) ------------
// grid = NODES/16 = 512, block = 224 (200 active).
__global__ __launch_bounds__(224, 3) void gru_kernel(const float* __restrict__ hin,
                                                     float* __restrict__ hout,
                                                     const float* __restrict__ b_ih,
                                                     const float* __restrict__ b_hh) {
    __shared__ __align__(16) float sh_mT[HH][16];   // 6.4KB
    __shared__ __align__(16) float sh_hT[HH][16];   // 6.4KB

    const int tid = threadIdx.x;
    const int p0  = blockIdx.x * 16;

    for (int idx = tid; idx < HH*4; idx += 224) {   // 400 float4 per array
        int k = idx >> 2, q = idx & 3;
        ((float4*)&sh_mT[k][0])[q] = ((const float4*)(g_msgT + (size_t)k*NODES + p0))[q];
        ((float4*)&sh_hT[k][0])[q] = ((const float4*)(hin   + (size_t)k*NODES + p0))[q];
    }
    __syncthreads();

    if (tid < 200) {
        const int h  = tid % HH;
        const int n0 = (tid / HH) * 8;
        ull gi0[4], gi1[4], gi2[4], gh0[4], gh1[4], gh2[4];
        #pragma unroll
        for (int j = 0; j < 4; j++) { gi0[j]=0; gi1[j]=0; gi2[j]=0; gh0[j]=0; gh1[j]=0; gh2[j]=0; }

        for (int k = 0; k < HH; k++) {
            ull wi0 = g_WihP[k*H3 + h];
            ull wi1 = g_WihP[k*H3 + 100 + h];
            ull wi2 = g_WihP[k*H3 + 200 + h];
            ull wh0 = g_WhhP[k*H3 + h];
            ull wh1 = g_WhhP[k*H3 + 100 + h];
            ull wh2 = g_WhhP[k*H3 + 200 + h];
            const ulonglong2* mp = (const ulonglong2*)&sh_mT[k][n0];
            const ulonglong2* hp = (const ulonglong2*)&sh_hT[k][n0];
            ulonglong2 m0 = mp[0], m1 = mp[1];
            ulonglong2 h0 = hp[0], h1 = hp[1];
            fma2(gi0[0], wi0, m0.x); fma2(gi0[1], wi0, m0.y); fma2(gi0[2], wi0, m1.x); fma2(gi0[3], wi0, m1.y);
            fma2(gi1[0], wi1, m0.x); fma2(gi1[1], wi1, m0.y); fma2(gi1[2], wi1, m1.x); fma2(gi1[3], wi1, m1.y);
            fma2(gi2[0], wi2, m0.x); fma2(gi2[1], wi2, m0.y); fma2(gi2[2], wi2, m1.x); fma2(gi2[3], wi2, m1.y);
            fma2(gh0[0], wh0, h0.x); fma2(gh0[1], wh0, h0.y); fma2(gh0[2], wh0, h1.x); fma2(gh0[3], wh0, h1.y);
            fma2(gh1[0], wh1, h0.x); fma2(gh1[1], wh1, h0.y); fma2(gh1[2], wh1, h1.x); fma2(gh1[3], wh1, h1.y);
            fma2(gh2[0], wh2, h0.x); fma2(gh2[1], wh2, h0.y); fma2(gh2[2], wh2, h1.x); fma2(gh2[3], wh2, h1.y);
        }

        const float bi0 = b_ih[h], bi1 = b_ih[100+h], bi2 = b_ih[200+h];
        const float bh0 = b_hh[h], bh1 = b_hh[100+h], bh2 = b_hh[200+h];
        const ulonglong2* hvp = (const ulonglong2*)&sh_hT[h][n0];
        ulonglong2 hv01 = hvp[0], hv23 = hvp[1];
        ull hvs[4] = {hv01.x, hv01.y, hv23.x, hv23.y};

        ull outp[4];
        #pragma unroll
        for (int j = 0; j < 4; j++) {
            float irl, irh, izl, izh, inl, inh, hrl, hrh, hzl, hzh, hnl, hnh, hvl, hvh;
            unpack2(gi0[j], irl, irh); unpack2(gi1[j], izl, izh); unpack2(gi2[j], inl, inh);
            unpack2(gh0[j], hrl, hrh); unpack2(gh1[j], hzl, hzh); unpack2(gh2[j], hnl, hnh);
            unpack2(hvs[j], hvl, hvh);
            int pA = p0 + n0 + 2*j, pB = pA + 1;
            float ol, oh;
            {
                float r = sigmf(irl + bi0 + hrl + bh0);
                float z = sigmf(izl + bi1 + hzl + bh1);
                float n = tanhf(inl + bi2 + r*(hnl + bh2));
                ol = (g_cnt[pA] == 0) ? hvl : (1.0f - z)*n + z*hvl;
            }
            {
                float r = sigmf(irh + bi0 + hrh + bh0);
                float z = sigmf(izh + bi1 + hzh + bh1);
                float n = tanhf(inh + bi2 + r*(hnh + bh2));
                oh = (g_cnt[pB] == 0) ? hvh : (1.0f - z)*n + z*hvh;
            }
            outp[j] = pack2(ol, oh);
        }
        ulonglong2* dst = (ulonglong2*)(hout + (size_t)h*NODES + p0 + n0);
        dst[0] = make_ulonglong2(outp[0], outp[1]);
        dst[1] = make_ulonglong2(outp[2], outp[3]);
    }
}

// ---------------- readout ----------------
// grid = BB, block = 256
__global__ __launch_bounds__(256) void readout_kernel(const float* __restrict__ hfin,
                                                      const float* __restrict__ nodes,
                                                      const float* __restrict__ Wg,
                                                      const float* __restrict__ bg,
                                                      const float* __restrict__ We,
                                                      const float* __restrict__ be,
                                                      const float* __restrict__ Wo,
                                                      const float* __restrict__ bo,
                                                      float* __restrict__ out) {
    __shared__ __align__(16) float sh_hT[HH][NN];   // 12.8KB
    __shared__ __align__(16) float sh_xT[FF][NN];   // 5.1KB
    __shared__ float sh_part[2][HH];
    __shared__ float sh_acc[HH];

    const int b = blockIdx.x;
    const int tid = threadIdx.x;
    const int p0 = b * NN;

    for (int idx = tid; idx < HH*(NN/4); idx += 256) {
        int k = idx >> 3, q = idx & 7;
        ((float4*)&sh_hT[k][0])[q] = ((const float4*)(hfin + (size_t)k*NODES + p0))[q];
    }
    for (int idx = tid; idx < NN*FF; idx += 256) {
        int n = idx & 31, k = idx >> 5;
        sh_xT[k][n] = nodes[(size_t)(p0 + n)*FF + k];
    }
    __syncthreads();

    if (tid < 200) {
        const int h   = tid % HH;
        const int grp = tid / HH;
        const int n0  = grp * 16;
        ull ga[8], ev[8];
        #pragma unroll
        for (int j = 0; j < 8; j++) { ga[j] = 0; ev[j] = 0; }
        for (int k = 0; k < HH; k++) {
            ull wg = packdup(Wg[k*HH + h]);
            ull we = packdup(We[k*HH + h]);
            const ulonglong2* hp = (const ulonglong2*)&sh_hT[k][n0];
            ulonglong2 a = hp[0], bq = hp[1], c = hp[2], d = hp[3];
            fma2(ga[0], wg, a.x); fma2(ga[1], wg, a.y); fma2(ga[2], wg, bq.x); fma2(ga[3], wg, bq.y);
            fma2(ga[4], wg, c.x); fma2(ga[5], wg, c.y); fma2(ga[6], wg, d.x);  fma2(ga[7], wg, d.y);
            fma2(ev[0], we, a.x); fma2(ev[1], we, a.y); fma2(ev[2], we, bq.x); fma2(ev[3], we, bq.y);
            fma2(ev[4], we, c.x); fma2(ev[5], we, c.y); fma2(ev[6], we, d.x);  fma2(ev[7], we, d.y);
        }
        for (int k = 0; k < FF; k++) {
            ull wg = packdup(Wg[(HH + k)*HH + h]);
            const ulonglong2* xp = (const ulonglong2*)&sh_xT[k][n0];
            ulonglong2 a = xp[0], bq = xp[1], c = xp[2], d = xp[3];
            fma2(ga[0], wg, a.x); fma2(ga[1], wg, a.y); fma2(ga[2], wg, bq.x); fma2(ga[3], wg, bq.y);
            fma2(ga[4], wg, c.x); fma2(ga[5], wg, c.y); fma2(ga[6], wg, d.x);  fma2(ga[7], wg, d.y);
        }
        float bgv = bg[h];
        float bev = be[h];
        float s = 0.f;
        #pragma unroll
        for (int j = 0; j < 8; j++) {
            float gl, gh_, el, eh;
            unpack2(ga[j], gl, gh_);
            unpack2(ev[j], el, eh);
            int pA = p0 + n0 + 2*j, pB = pA + 1;
            if (g_cnt[pA] != 0) s += sigmf(gl + bgv) * (el + bev);
            if (g_cnt[pB] != 0) s += sigmf(gh_ + bgv) * (eh + bev);
        }
        sh_part[grp][h] = s;
    }
    __syncthreads();
    if (tid < HH) sh_acc[tid] = sh_part[0][tid] + sh_part[1][tid];
    __syncthreads();

    for (int o = tid; o < OUTD; o += 256) {
        float v = bo[o];
        #pragma unroll 4
        for (int k = 0; k < HH; k++) v += sh_acc[k] * Wo[k*OUTD + o];
        out[(size_t)b*OUTD + o] = v;
    }
}

// ---------------- launcher ----------------
extern "C" void kernel_launch(void* const* d_in, const int* in_sizes, int n_in,
                              void* d_out, int out_size) {
    const float* nodes = (const float*)d_in[0];
    const float* edges = (const float*)d_in[1];
    const float* W_msg = (const float*)d_in[2];
    const float* W_ih  = (const float*)d_in[3];
    const float* W_hh  = (const float*)d_in[4];
    const float* b_ih  = (const float*)d_in[5];
    const float* b_hh  = (const float*)d_in[6];
    const float* Wg    = (const float*)d_in[7];
    const float* bg    = (const float*)d_in[8];
    const float* We    = (const float*)d_in[9];
    const float* be    = (const float*)d_in[10];
    const float* Wo    = (const float*)d_in[11];
    const float* bo    = (const float*)d_in[12];
    float* out = (float*)d_out;

    float *hA, *hB;
    cudaGetSymbolAddress((void**)&hA, g_hA);
    cudaGetSymbolAddress((void**)&hB, g_hB);

    prep_weights<<<(100000 + 255) / 256, 256>>>(W_msg, W_ih, W_hh);
    prep_edges<<<(NODES*32 + 255) / 256, 256>>>(edges);
    init_hidden<<<(NODES*HH + 255) / 256, 256>>>(nodes);

    // pass 1
    msg_kernel<<<BB, 416>>>(hA);
    gru_kernel<<<NODES/16, 224>>>(hA, hB, b_ih, b_hh);
    // pass 2
    msg_kernel<<<BB, 416>>>(hB);
    gru_kernel<<<NODES/16, 224>>>(hB, hA, b_ih, b_hh);
    // pass 3
    msg_kernel<<<BB, 416>>>(hA);
    gru_kernel<<<NODES/16, 224>>>(hA, hB, b_ih, b_hh);

    readout_kernel<<<BB, 256>>>(hB, nodes, Wg, bg, We, be, Wo, bo, out);
}

// round 4
// speedup vs baseline: 1.1165x; 1.1165x over previous
#include <cuda_runtime.h>
#include <math.h>

#define BB    256
#define NN    32
#define FF    40
#define HH    100
#define MM    100
#define EFN   4
#define OUTD  128
#define H3    300
#define KMAX  8
#define NODES (BB*NN)   // 8192
#define ECAP  16384
#define EPB   64

typedef unsigned long long ull;

// ---------------- device scratch ----------------
__device__ __align__(16) float g_hTA[HH*NODES];      // transposed [h][p]
__device__ __align__(16) float g_hTB[HH*NODES];
__device__ __align__(16) float g_hNA[NODES*HH];      // node-major [p][h]
__device__ __align__(16) float g_hNB[NODES*HH];
__device__ __align__(16) float g_emsg[4*ECAP*MM];    // [slot][m], 26MB
__device__ __align__(16) float g_Wm[EFN*HH*MM];      // [f][k][m]
__device__ __align__(16) float g_WihT[MM*H3];        // [k][r]
__device__ __align__(16) float g_WhhT[HH*H3];        // [k][r]
__device__ int   g_esrc[4*ECAP];
__device__ int   g_ecnt[4];
__device__ int   g_slotid[NODES*KMAX];
__device__ float g_wgt[NODES*KMAX];
__device__ int   g_cnt[NODES];

__device__ __forceinline__ float sigmf(float x) { return 1.0f / (1.0f + expf(-x)); }
__device__ __forceinline__ ull packdup(float w) {
    ull r; asm("mov.b64 %0,{%1,%1};" : "=l"(r) : "f"(w)); return r;
}
__device__ __forceinline__ void unpack2(ull v, float& lo, float& hi) {
    asm("mov.b64 {%0,%1},%2;" : "=f"(lo), "=f"(hi) : "l"(v));
}
__device__ __forceinline__ void fma2(ull& d, ull a, ull b) {
    asm("fma.rn.f32x2 %0, %1, %2, %0;" : "+l"(d) : "l"(a), "l"(b));
}

// ---------------- prep: weight layouts + zero edge counters ----------------
__global__ void prep_weights(const float* __restrict__ W_msg,
                             const float* __restrict__ W_ih,
                             const float* __restrict__ W_hh) {
    int gid = blockIdx.x * blockDim.x + threadIdx.x;
    const int NWT = EFN*HH*MM;            // 40000
    const int NWI = MM*H3;                // 30000
    if (gid < 4) g_ecnt[gid] = 0;
    if (gid < NWT) {
        int f = gid / (HH*MM);
        int rem = gid % (HH*MM);
        int k = rem / MM;
        int m = rem % MM;
        g_Wm[gid] = W_msg[(m*HH + k)*EFN + f];
    } else if (gid < NWT + NWI) {
        int t = gid - NWT;
        int k = t / H3, r = t % H3;
        g_WihT[t] = W_ih[r*MM + k];
    } else if (gid < NWT + NWI + HH*H3) {
        int t = gid - NWT - NWI;
        int k = t / H3, r = t % H3;
        g_WhhT[t] = W_hh[r*HH + k];
    }
}

// ---------------- prep: edge lists + type-sorted slot assignment ----------
__global__ void prep_edges(const float* __restrict__ edges) {
    int warp = (blockIdx.x * blockDim.x + threadIdx.x) >> 5;
    int lane = threadIdx.x & 31;
    if (warp >= NODES) return;
    int p = warp;
    int base = p & ~(NN-1);                 // batch start node
    float4 v = ((const float4*)edges)[(size_t)p * NN + lane];
    float vv[4] = {v.x, v.y, v.z, v.w};
    int nl = (vv[0]!=0.f) + (vv[1]!=0.f) + (vv[2]!=0.f) + (vv[3]!=0.f);
    int inc = nl;
    #pragma unroll
    for (int off = 1; off < 32; off <<= 1) {
        int t = __shfl_up_sync(0xFFFFFFFFu, inc, off);
        if (lane >= off) inc += t;
    }
    int excl = inc - nl;
    int total = __shfl_sync(0xFFFFFFFFu, inc, 31);
    int c = excl;
    #pragma unroll
    for (int f = 0; f < EFN; f++) {
        if (vv[f] != 0.f && c < KMAX) {
            int slot = atomicAdd(&g_ecnt[f], 1);
            if (slot < ECAP) {
                g_esrc[f*ECAP + slot] = base + lane;   // src node = neighbor g
                g_slotid[p*KMAX + c] = f*ECAP + slot;
                g_wgt[p*KMAX + c] = vv[f];
                c++;
            }
        }
    }
    if (lane == 0) g_cnt[p] = (total < KMAX) ? total : KMAX;
}

// ---------------- init hidden (both layouts) ----------------
__global__ void init_hidden(const float* __restrict__ nodes) {
    int gid = blockIdx.x * blockDim.x + threadIdx.x;
    if (gid >= NODES*HH) return;
    int p = gid % NODES;
    int h = gid / NODES;
    float v = (h < FF) ? nodes[p*FF + h] : 0.0f;
    g_hTA[(size_t)h*NODES + p] = v;
    g_hNA[(size_t)p*HH + h] = v;
}

// ---------------- messages: type-sorted edge GEMM ----------------
// grid = 4 * (ECAP/EPB) = 1024, block = 224 (200 active).
__global__ __launch_bounds__(224) void msg_kernel(const float* __restrict__ hN) {
    // reused: gather [k][68] (27.2KB) then output stage [64][100] (25.6KB)
    __shared__ __align__(16) float sh[100*68];

    const int bid = blockIdx.x;
    const int f   = bid >> 8;
    const int e0  = (bid & 255) * EPB;
    const int cnt = g_ecnt[f];
    if (e0 >= cnt) return;
    const int tid = threadIdx.x;

    // gather neighbor hidden, transposed to [k][e]
    for (int idx = tid; idx < 64*25; idx += 224) {
        int e = idx & 63;
        int q = idx >> 6;
        int ee = e0 + e;
        int src = (ee < cnt) ? g_esrc[f*ECAP + ee] : 0;
        float4 v = ((const float4*)(hN + (size_t)src*HH))[q];
        sh[(q*4+0)*68 + e] = v.x;
        sh[(q*4+1)*68 + e] = v.y;
        sh[(q*4+2)*68 + e] = v.z;
        sh[(q*4+3)*68 + e] = v.w;
    }
    __syncthreads();

    ull acc[16];
    int m = 0, eg = 0;
    if (tid < 200) {
        m = tid % 100; eg = tid / 100;
        #pragma unroll
        for (int j = 0; j < 16; j++) acc[j] = 0ull;
        const float* Wf = g_Wm + (size_t)f*HH*MM + m;
        for (int k = 0; k < HH; k++) {
            ull w = packdup(Wf[k*MM]);
            const ulonglong2* hp = (const ulonglong2*)&sh[k*68 + eg*32];
            ulonglong2 a = hp[0], b = hp[1], c2 = hp[2], d = hp[3];
            fma2(acc[0], w, a.x);  fma2(acc[1], w, a.y);
            fma2(acc[2], w, b.x);  fma2(acc[3], w, b.y);
            fma2(acc[4], w, c2.x); fma2(acc[5], w, c2.y);
            fma2(acc[6], w, d.x);  fma2(acc[7], w, d.y);
            // second 16 edges
            const ulonglong2* hp2 = hp + 4;
            ulonglong2 a2 = hp2[0], b2 = hp2[1], c3 = hp2[2], d2 = hp2[3];
            fma2(acc[8],  w, a2.x); fma2(acc[9],  w, a2.y);
            fma2(acc[10], w, b2.x); fma2(acc[11], w, b2.y);
            fma2(acc[12], w, c3.x); fma2(acc[13], w, c3.y);
            fma2(acc[14], w, d2.x); fma2(acc[15], w, d2.y);
        }
    }
    __syncthreads();
    // stage transposed output [e][m]
    if (tid < 200) {
        #pragma unroll
        for (int j = 0; j < 16; j++) {
            float lo, hi; unpack2(acc[j], lo, hi);
            int e = eg*32 + 2*j;
            sh[e*100 + m]     = lo;
            sh[(e+1)*100 + m] = hi;
        }
    }
    __syncthreads();
    // coalesced store to emsg[slot][m]
    float4* out4 = (float4*)g_emsg;
    for (int idx = tid; idx < 1600; idx += 224) {
        int e = idx / 25, q = idx % 25;
        int slot = f*ECAP + e0 + e;
        const float* row = sh + e*100 + q*4;
        out4[(size_t)slot*25 + q] = make_float4(row[0], row[1], row[2], row[3]);
    }
}

// ---------------- GRU: 16 nodes/block, row-parallel GEMM ----------------
// grid = NODES/16 = 512, block = 320 (300 active in GEMM).
__global__ __launch_bounds__(320) void gru_kernel(const float* __restrict__ hT_in,
                                                  float* __restrict__ hT_out,
                                                  float* __restrict__ hN_out,
                                                  const float* __restrict__ b_ih,
                                                  const float* __restrict__ b_hh) {
    __shared__ __align__(16) float sh_h[HH*16];     // [k][n] 6.4KB
    __shared__ __align__(16) float sh_ov[16*H3*2];  // overlay: msg [k][16] -> gi/gh [16][300]
    __shared__ int   sh_slot[16][KMAX];
    __shared__ float sh_w[16][KMAX];
    __shared__ int   sh_c[16];

    float* sh_m  = sh_ov;            // [k][16]
    float* sh_gi = sh_ov;            // [16][300]
    float* sh_gh = sh_ov + 16*H3;

    const int tid = threadIdx.x;
    const int p0  = blockIdx.x * 16;

    if (tid < 16) sh_c[tid] = g_cnt[p0 + tid];
    else if (tid >= 32 && tid < 160) {
        int t = tid - 32; int n = t >> 3, e = t & 7;
        sh_slot[n][e] = g_slotid[(p0+n)*KMAX + e];
        sh_w[n][e]    = g_wgt[(p0+n)*KMAX + e];
    }
    for (int idx = tid; idx < 400; idx += 320) {
        int k = idx >> 2, q = idx & 3;
        ((float4*)&sh_h[k*16])[q] = ((const float4*)(hT_in + (size_t)k*NODES + p0))[q];
    }
    __syncthreads();

    // gather messages: per (kq, n) sum node's weighted edge rows
    const float4* em4 = (const float4*)g_emsg;
    for (int idx = tid; idx < 400; idx += 320) {
        int kq = idx >> 4, n = idx & 15;
        float ax = 0.f, ay = 0.f, az = 0.f, aw = 0.f;
        int c = sh_c[n];
        for (int e = 0; e < c; e++) {
            int s = sh_slot[n][e];
            float w = sh_w[n][e];
            float4 v = em4[(size_t)s*25 + kq];
            ax += w*v.x; ay += w*v.y; az += w*v.z; aw += w*v.w;
        }
        sh_m[(kq*4+0)*16 + n] = ax;
        sh_m[(kq*4+1)*16 + n] = ay;
        sh_m[(kq*4+2)*16 + n] = az;
        sh_m[(kq*4+3)*16 + n] = aw;
    }
    __syncthreads();

    // GEMM: thread r computes gi[r], gh[r] over 16 nodes
    ull gi[8], gh[8];
    if (tid < H3) {
        const int r = tid;
        #pragma unroll
        for (int j = 0; j < 8; j++) { gi[j] = 0ull; gh[j] = 0ull; }
        for (int k = 0; k < HH; k++) {
            ull wi = packdup(g_WihT[k*H3 + r]);
            ull wh = packdup(g_WhhT[k*H3 + r]);
            const ulonglong2* mp = (const ulonglong2*)&sh_m[k*16];
            const ulonglong2* hp = (const ulonglong2*)&sh_h[k*16];
            ulonglong2 m01 = mp[0], m23 = mp[1];
            ulonglong2 h01 = hp[0], h23 = hp[1];
            fma2(gi[0], wi, m01.x); fma2(gi[1], wi, m01.y);
            fma2(gi[2], wi, m23.x); fma2(gi[3], wi, m23.y);
            fma2(gh[0], wh, h01.x); fma2(gh[1], wh, h01.y);
            fma2(gh[2], wh, h23.x); fma2(gh[3], wh, h23.y);
            // upper 8 nodes
            ulonglong2 m45 = mp[2], m67 = mp[3];
            ulonglong2 h45 = hp[2], h67 = hp[3];
            fma2(gi[4], wi, m45.x); fma2(gi[5], wi, m45.y);
            fma2(gi[6], wi, m67.x); fma2(gi[7], wi, m67.y);
            fma2(gh[4], wh, h45.x); fma2(gh[5], wh, h45.y);
            fma2(gh[6], wh, h67.x); fma2(gh[7], wh, h67.y);
        }
    }
    __syncthreads();   // done reading sh_m; safe to overwrite with gi/gh
    if (tid < H3) {
        const int r = tid;
        #pragma unroll
        for (int j = 0; j < 8; j++) {
            float lo, hi;
            unpack2(gi[j], lo, hi);
            sh_gi[(2*j)*H3 + r]   = lo;
            sh_gi[(2*j+1)*H3 + r] = hi;
            unpack2(gh[j], lo, hi);
            sh_gh[(2*j)*H3 + r]   = lo;
            sh_gh[(2*j+1)*H3 + r] = hi;
        }
    }
    __syncthreads();

    // elementwise GRU + dual-layout store
    for (int idx = tid; idx < 1600; idx += 320) {
        int h = idx >> 4, n = idx & 15;
        int p = p0 + n;
        float hval = sh_h[h*16 + n];
        float o;
        if (sh_c[n] == 0) {
            o = hval;
        } else {
            float r_ = sigmf(sh_gi[n*H3 + h]       + b_ih[h]       + sh_gh[n*H3 + h]       + b_hh[h]);
            float z  = sigmf(sh_gi[n*H3 + 100 + h] + b_ih[100 + h] + sh_gh[n*H3 + 100 + h] + b_hh[100 + h]);
            float nn2 = tanhf(sh_gi[n*H3 + 200 + h] + b_ih[200 + h] + r_*(sh_gh[n*H3 + 200 + h] + b_hh[200 + h]));
            o = (1.0f - z)*nn2 + z*hval;
        }
        hT_out[(size_t)h*NODES + p] = o;
        hN_out[(size_t)p*HH + h]    = o;
    }
}

// ---------------- readout ----------------
__global__ __launch_bounds__(256) void readout_kernel(const float* __restrict__ hfin,
                                                      const float* __restrict__ nodes,
                                                      const float* __restrict__ Wg,
                                                      const float* __restrict__ bg,
                                                      const float* __restrict__ We,
                                                      const float* __restrict__ be,
                                                      const float* __restrict__ Wo,
                                                      const float* __restrict__ bo,
                                                      float* __restrict__ out) {
    __shared__ __align__(16) float sh_hT[HH][NN];
    __shared__ __align__(16) float sh_xT[FF][NN];
    __shared__ float sh_part[2][HH];
    __shared__ float sh_acc[HH];

    const int b = blockIdx.x;
    const int tid = threadIdx.x;
    const int p0 = b * NN;

    for (int idx = tid; idx < HH*(NN/4); idx += 256) {
        int k = idx >> 3, q = idx & 7;
        ((float4*)&sh_hT[k][0])[q] = ((const float4*)(hfin + (size_t)k*NODES + p0))[q];
    }
    for (int idx = tid; idx < NN*FF; idx += 256) {
        int n = idx & 31, k = idx >> 5;
        sh_xT[k][n] = nodes[(size_t)(p0 + n)*FF + k];
    }
    __syncthreads();

    if (tid < 200) {
        const int h   = tid % HH;
        const int grp = tid / HH;
        const int n0  = grp * 16;
        ull ga[8], ev[8];
        #pragma unroll
        for (int j = 0; j < 8; j++) { ga[j] = 0; ev[j] = 0; }
        for (int k = 0; k < HH; k++) {
            ull wg = packdup(Wg[k*HH + h]);
            ull we = packdup(We[k*HH + h]);
            const ulonglong2* hp = (const ulonglong2*)&sh_hT[k][n0];
            ulonglong2 a = hp[0], bq = hp[1], c = hp[2], d = hp[3];
            fma2(ga[0], wg, a.x); fma2(ga[1], wg, a.y); fma2(ga[2], wg, bq.x); fma2(ga[3], wg, bq.y);
            fma2(ga[4], wg, c.x); fma2(ga[5], wg, c.y); fma2(ga[6], wg, d.x);  fma2(ga[7], wg, d.y);
            fma2(ev[0], we, a.x); fma2(ev[1], we, a.y); fma2(ev[2], we, bq.x); fma2(ev[3], we, bq.y);
            fma2(ev[4], we, c.x); fma2(ev[5], we, c.y); fma2(ev[6], we, d.x);  fma2(ev[7], we, d.y);
        }
        for (int k = 0; k < FF; k++) {
            ull wg = packdup(Wg[(HH + k)*HH + h]);
            const ulonglong2* xp = (const ulonglong2*)&sh_xT[k][n0];
            ulonglong2 a = xp[0], bq = xp[1], c = xp[2], d = xp[3];
            fma2(ga[0], wg, a.x); fma2(ga[1], wg, a.y); fma2(ga[2], wg, bq.x); fma2(ga[3], wg, bq.y);
            fma2(ga[4], wg, c.x); fma2(ga[5], wg, c.y); fma2(ga[6], wg, d.x);  fma2(ga[7], wg, d.y);
        }
        float bgv = bg[h];
        float bev = be[h];
        float s = 0.f;
        #pragma unroll
        for (int j = 0; j < 8; j++) {
            float gl, gh_, el, eh;
            unpack2(ga[j], gl, gh_);
            unpack2(ev[j], el, eh);
            int pA = p0 + n0 + 2*j, pB = pA + 1;
            if (g_cnt[pA] != 0) s += sigmf(gl + bgv) * (el + bev);
            if (g_cnt[pB] != 0) s += sigmf(gh_ + bgv) * (eh + bev);
        }
        sh_part[grp][h] = s;
    }
    __syncthreads();
    if (tid < HH) sh_acc[tid] = sh_part[0][tid] + sh_part[1][tid];
    __syncthreads();

    for (int o = tid; o < OUTD; o += 256) {
        float v = bo[o];
        #pragma unroll 4
        for (int k = 0; k < HH; k++) v += sh_acc[k] * Wo[k*OUTD + o];
        out[(size_t)b*OUTD + o] = v;
    }
}

// ---------------- launcher ----------------
extern "C" void kernel_launch(void* const* d_in, const int* in_sizes, int n_in,
                              void* d_out, int out_size) {
    const float* nodes = (const float*)d_in[0];
    const float* edges = (const float*)d_in[1];
    const float* W_msg = (const float*)d_in[2];
    const float* W_ih  = (const float*)d_in[3];
    const float* W_hh  = (const float*)d_in[4];
    const float* b_ih  = (const float*)d_in[5];
    const float* b_hh  = (const float*)d_in[6];
    const float* Wg    = (const float*)d_in[7];
    const float* bg    = (const float*)d_in[8];
    const float* We    = (const float*)d_in[9];
    const float* be    = (const float*)d_in[10];
    const float* Wo    = (const float*)d_in[11];
    const float* bo    = (const float*)d_in[12];
    float* out = (float*)d_out;

    float *hTA, *hTB, *hNA, *hNB;
    cudaGetSymbolAddress((void**)&hTA, g_hTA);
    cudaGetSymbolAddress((void**)&hTB, g_hTB);
    cudaGetSymbolAddress((void**)&hNA, g_hNA);
    cudaGetSymbolAddress((void**)&hNB, g_hNB);

    prep_weights<<<(100000 + 255) / 256, 256>>>(W_msg, W_ih, W_hh);
    prep_edges<<<(NODES*32 + 255) / 256, 256>>>(edges);
    init_hidden<<<(NODES*HH + 255) / 256, 256>>>(nodes);

    const int MGRID = 4 * (ECAP / EPB);   // 1024

    // pass 1
    msg_kernel<<<MGRID, 224>>>(hNA);
    gru_kernel<<<NODES/16, 320>>>(hTA, hTB, hNB, b_ih, b_hh);
    // pass 2
    msg_kernel<<<MGRID, 224>>>(hNB);
    gru_kernel<<<NODES/16, 320>>>(hTB, hTA, hNA, b_ih, b_hh);
    // pass 3
    msg_kernel<<<MGRID, 224>>>(hNA);
    gru_kernel<<<NODES/16, 320>>>(hTA, hTB, hNB, b_ih, b_hh);

    readout_kernel<<<BB, 256>>>(hTB, nodes, Wg, bg, We, be, Wo, bo, out);
}

// round 5
// speedup vs baseline: 1.4939x; 1.3380x over previous
#include <cuda_runtime.h>
#include <math.h>

#define BB    256
#define NN    32
#define FF    40
#define HH    100
#define MM    100
#define EFN   4
#define OUTD  128
#define H3    300
#define KMAX  8
#define NODES (BB*NN)   // 8192
#define TPAD  34        // T row pad (2-way bank conflict on 8B stores)
#define SPAD  601       // gate staging row stride (odd -> conflict-free)
#define NTHR  416

typedef unsigned long long ull;

// ---------------- device scratch ----------------
__device__ __align__(16) float g_Wm[EFN*HH*MM];   // [f][k][m]
__device__ __align__(16) float g_WihT[MM*H3];     // [k][r]
__device__ __align__(16) float g_WhhT[HH*H3];     // [k][r]
__device__ int   g_nbr[NODES*KMAX];               // local neighbor idx 0..31
__device__ int   g_typ[NODES*KMAX];
__device__ float g_wgt[NODES*KMAX];
__device__ int   g_cnt[NODES];

__device__ __forceinline__ float sigmf(float x) { return 1.0f / (1.0f + expf(-x)); }
__device__ __forceinline__ ull packdup(float w) {
    ull r; asm("mov.b64 %0,{%1,%1};" : "=l"(r) : "f"(w)); return r;
}
__device__ __forceinline__ void unpack2(ull v, float& lo, float& hi) {
    asm("mov.b64 {%0,%1},%2;" : "=f"(lo), "=f"(hi) : "l"(v));
}
__device__ __forceinline__ void fma2(ull& d, ull a, ull b) {
    asm("fma.rn.f32x2 %0, %1, %2, %0;" : "+l"(d) : "l"(a), "l"(b));
}

// ---------------- prep: weight layouts ----------------
__global__ void prep_weights(const float* __restrict__ W_msg,
                             const float* __restrict__ W_ih,
                             const float* __restrict__ W_hh) {
    int gid = blockIdx.x * blockDim.x + threadIdx.x;
    const int NWT = EFN*HH*MM;            // 40000
    const int NWI = MM*H3;                // 30000
    if (gid < NWT) {
        int f = gid / (HH*MM);
        int rem = gid % (HH*MM);
        int k = rem / MM;
        int m = rem % MM;
        g_Wm[gid] = W_msg[(m*HH + k)*EFN + f];
    } else if (gid < NWT + NWI) {
        int t = gid - NWT;
        int k = t / H3, r = t % H3;
        g_WihT[t] = W_ih[r*MM + k];
    } else if (gid < NWT + NWI + HH*H3) {
        int t = gid - NWT - NWI;
        int k = t / H3, r = t % H3;
        g_WhhT[t] = W_hh[r*HH + k];
    }
}

// ---------------- prep: compact edge lists (warp per node) ----------------
__global__ void prep_edges(const float* __restrict__ edges) {
    int warp = (blockIdx.x * blockDim.x + threadIdx.x) >> 5;
    int lane = threadIdx.x & 31;
    if (warp >= NODES) return;
    int p = warp;
    float4 v = ((const float4*)edges)[(size_t)p * NN + lane];
    float vv[4] = {v.x, v.y, v.z, v.w};
    int nl = (vv[0]!=0.f) + (vv[1]!=0.f) + (vv[2]!=0.f) + (vv[3]!=0.f);
    int inc = nl;
    #pragma unroll
    for (int off = 1; off < 32; off <<= 1) {
        int t = __shfl_up_sync(0xFFFFFFFFu, inc, off);
        if (lane >= off) inc += t;
    }
    int excl = inc - nl;
    int total = __shfl_sync(0xFFFFFFFFu, inc, 31);
    int c = excl;
    #pragma unroll
    for (int f = 0; f < EFN; f++) {
        if (vv[f] != 0.f && c < KMAX) {
            g_nbr[p*KMAX + c] = lane;      // local index within batch
            g_typ[p*KMAX + c] = f;
            g_wgt[p*KMAX + c] = vv[f];
            c++;
        }
    }
    if (lane == 0) g_cnt[p] = (total < KMAX) ? total : KMAX;
}

// ---------------- fused: 3 passes + readout, one block per batch ----------
__global__ __launch_bounds__(NTHR, 2) void fused_kernel(
        const float* __restrict__ nodes,
        const float* __restrict__ b_ih, const float* __restrict__ b_hh,
        const float* __restrict__ Wg,   const float* __restrict__ bg,
        const float* __restrict__ We,   const float* __restrict__ be,
        const float* __restrict__ Wo,   const float* __restrict__ bo,
        float* __restrict__ out) {
    __shared__ __align__(16) float sh_h[HH*NN];        // [k][n] 12.8KB
    __shared__ __align__(16) float sh_m[HH*NN];        // [k][n] 12.8KB (x-stage in readout)
    __shared__ __align__(16) float sh_T[EFN*MM*TPAD];  // 54.4KB (T / gate staging overlay)
    __shared__ int   sh_nbr[NN][KMAX];
    __shared__ int   sh_typ[NN][KMAX];
    __shared__ float sh_wgt[NN][KMAX];
    __shared__ int   sh_cnt[NN];
    __shared__ float sh_part[2*HH];
    __shared__ float sh_acc[HH];

    const int b   = blockIdx.x;
    const int tid = threadIdx.x;
    const int p0  = b * NN;

    // edge meta
    if (tid < NN) sh_cnt[tid] = g_cnt[p0 + tid];
    else if (tid >= 32 && tid < 32 + NN*KMAX) {
        int t = tid - 32; int n = t >> 3, e = t & 7;
        sh_nbr[n][e] = g_nbr[(p0+n)*KMAX + e];
        sh_typ[n][e] = g_typ[(p0+n)*KMAX + e];
        sh_wgt[n][e] = g_wgt[(p0+n)*KMAX + e];
    }
    // hidden init: [nodes | 0]
    for (int idx = tid; idx < HH*NN; idx += NTHR) {
        int k = idx >> 5, n = idx & 31;
        sh_h[idx] = (k < FF) ? nodes[(size_t)(p0+n)*FF + k] : 0.0f;
    }
    __syncthreads();

    for (int pass = 0; pass < 3; pass++) {
        // ---- T[f][m][n] = sum_k Wm[f][k][m] * h[k][n] ----
        if (tid < 400) {
            const int f = tid / 100, m = tid - f*100;
            ull acc[16];
            #pragma unroll
            for (int j = 0; j < 16; j++) acc[j] = 0ull;
            const float* W = g_Wm + (size_t)(f*HH)*MM + m;
            for (int k = 0; k < HH; k++) {
                ull w = packdup(W[k*MM]);
                const ulonglong2* hp = (const ulonglong2*)(sh_h + k*NN);
                ulonglong2 v0 = hp[0], v1 = hp[1], v2 = hp[2], v3 = hp[3];
                fma2(acc[0], w, v0.x); fma2(acc[1], w, v0.y);
                fma2(acc[2], w, v1.x); fma2(acc[3], w, v1.y);
                fma2(acc[4], w, v2.x); fma2(acc[5], w, v2.y);
                fma2(acc[6], w, v3.x); fma2(acc[7], w, v3.y);
                ulonglong2 v4 = hp[4], v5 = hp[5], v6 = hp[6], v7 = hp[7];
                fma2(acc[8],  w, v4.x); fma2(acc[9],  w, v4.y);
                fma2(acc[10], w, v5.x); fma2(acc[11], w, v5.y);
                fma2(acc[12], w, v6.x); fma2(acc[13], w, v6.y);
                fma2(acc[14], w, v7.x); fma2(acc[15], w, v7.y);
            }
            ull* Trow = (ull*)(sh_T + (size_t)(f*MM + m)*TPAD);
            #pragma unroll
            for (int j = 0; j < 16; j++) Trow[j] = acc[j];
        }
        __syncthreads();

        // ---- gather: msg[m][n] = sum_e w_e * T[f_e][m][g_e] ----
        if (tid < 400) {
            const int m = tid >> 2, ng = tid & 3;
            const int n0 = ng * 8;
            #pragma unroll
            for (int j = 0; j < 8; j++) {
                int n = n0 + j;
                int c = sh_cnt[n];
                float s = 0.f;
                for (int e = 0; e < c; e++) {
                    s += sh_wgt[n][e] *
                         sh_T[(size_t)(sh_typ[n][e]*MM + m)*TPAD + sh_nbr[n][e]];
                }
                sh_m[m*NN + n] = s;
            }
        }
        __syncthreads();

        // ---- GRU in two 16-node halves ----
        for (int half = 0; half < 2; half++) {
            const int n0 = half * 16;
            if (tid < H3) {
                const int r = tid;
                ull gi[8], gh[8];
                #pragma unroll
                for (int j = 0; j < 8; j++) { gi[j] = 0ull; gh[j] = 0ull; }
                for (int k = 0; k < HH; k++) {
                    ull wi = packdup(g_WihT[k*H3 + r]);
                    ull wh = packdup(g_WhhT[k*H3 + r]);
                    const ulonglong2* mp = (const ulonglong2*)(sh_m + k*NN + n0);
                    const ulonglong2* hp = (const ulonglong2*)(sh_h + k*NN + n0);
                    ulonglong2 m0 = mp[0], m1 = mp[1], m2 = mp[2], m3 = mp[3];
                    ulonglong2 h0 = hp[0], h1 = hp[1], h2 = hp[2], h3 = hp[3];
                    fma2(gi[0], wi, m0.x); fma2(gi[1], wi, m0.y);
                    fma2(gi[2], wi, m1.x); fma2(gi[3], wi, m1.y);
                    fma2(gi[4], wi, m2.x); fma2(gi[5], wi, m2.y);
                    fma2(gi[6], wi, m3.x); fma2(gi[7], wi, m3.y);
                    fma2(gh[0], wh, h0.x); fma2(gh[1], wh, h0.y);
                    fma2(gh[2], wh, h1.x); fma2(gh[3], wh, h1.y);
                    fma2(gh[4], wh, h2.x); fma2(gh[5], wh, h2.y);
                    fma2(gh[6], wh, h3.x); fma2(gh[7], wh, h3.y);
                }
                float* st = sh_T;   // staging overlay [16][SPAD]: gi | gh
                #pragma unroll
                for (int j = 0; j < 8; j++) {
                    float lo, hi;
                    unpack2(gi[j], lo, hi);
                    st[(2*j)*SPAD + r]       = lo;
                    st[(2*j+1)*SPAD + r]     = hi;
                    unpack2(gh[j], lo, hi);
                    st[(2*j)*SPAD + H3 + r]   = lo;
                    st[(2*j+1)*SPAD + H3 + r] = hi;
                }
            }
            __syncthreads();
            for (int idx = tid; idx < 1600; idx += NTHR) {
                int h = idx >> 4, ln = idx & 15;
                int n = n0 + ln;
                float hv = sh_h[h*NN + n];
                float o = hv;
                if (sh_cnt[n] != 0) {
                    const float* sr = sh_T + (size_t)ln*SPAD;
                    float r_ = sigmf(sr[h] + b_ih[h] + sr[H3 + h] + b_hh[h]);
                    float z  = sigmf(sr[100+h] + b_ih[100+h] + sr[H3+100+h] + b_hh[100+h]);
                    float nv = tanhf(sr[200+h] + b_ih[200+h] + r_*(sr[H3+200+h] + b_hh[200+h]));
                    o = (1.0f - z)*nv + z*hv;
                }
                sh_h[h*NN + n] = o;
            }
            __syncthreads();
        }
    }

    // ---- readout ----
    // stage x into sh_m rows [0..FF)
    for (int idx = tid; idx < FF*NN; idx += NTHR) {
        int k = idx >> 5, n = idx & 31;
        sh_m[k*NN + n] = nodes[(size_t)(p0+n)*FF + k];
    }
    __syncthreads();

    if (tid < 200) {
        const int grp = tid / HH;
        const int h   = tid - grp*HH;
        const int n0  = grp * 16;
        ull ga[8], ev[8];
        #pragma unroll
        for (int j = 0; j < 8; j++) { ga[j] = 0ull; ev[j] = 0ull; }
        for (int k = 0; k < HH; k++) {
            ull wg = packdup(Wg[k*HH + h]);
            ull we = packdup(We[k*HH + h]);
            const ulonglong2* hp = (const ulonglong2*)(sh_h + k*NN + n0);
            ulonglong2 a = hp[0], bq = hp[1], c = hp[2], d = hp[3];
            fma2(ga[0], wg, a.x); fma2(ga[1], wg, a.y); fma2(ga[2], wg, bq.x); fma2(ga[3], wg, bq.y);
            fma2(ga[4], wg, c.x); fma2(ga[5], wg, c.y); fma2(ga[6], wg, d.x);  fma2(ga[7], wg, d.y);
            fma2(ev[0], we, a.x); fma2(ev[1], we, a.y); fma2(ev[2], we, bq.x); fma2(ev[3], we, bq.y);
            fma2(ev[4], we, c.x); fma2(ev[5], we, c.y); fma2(ev[6], we, d.x);  fma2(ev[7], we, d.y);
        }
        for (int k = 0; k < FF; k++) {
            ull wg = packdup(Wg[(HH + k)*HH + h]);
            const ulonglong2* xp = (const ulonglong2*)(sh_m + k*NN + n0);
            ulonglong2 a = xp[0], bq = xp[1], c = xp[2], d = xp[3];
            fma2(ga[0], wg, a.x); fma2(ga[1], wg, a.y); fma2(ga[2], wg, bq.x); fma2(ga[3], wg, bq.y);
            fma2(ga[4], wg, c.x); fma2(ga[5], wg, c.y); fma2(ga[6], wg, d.x);  fma2(ga[7], wg, d.y);
        }
        float bgv = bg[h], bev = be[h];
        float s = 0.f;
        #pragma unroll
        for (int j = 0; j < 8; j++) {
            float gl, ghi, el, eh;
            unpack2(ga[j], gl, ghi);
            unpack2(ev[j], el, eh);
            int nA = n0 + 2*j, nB = nA + 1;
            if (sh_cnt[nA] != 0) s += sigmf(gl + bgv) * (el + bev);
            if (sh_cnt[nB] != 0) s += sigmf(ghi + bgv) * (eh + bev);
        }
        sh_part[grp*HH + h] = s;
    }
    __syncthreads();
    if (tid < HH) sh_acc[tid] = sh_part[tid] + sh_part[HH + tid];
    __syncthreads();

    if (tid < OUTD) {
        float v = bo[tid];
        #pragma unroll 4
        for (int k = 0; k < HH; k++) v += sh_acc[k] * Wo[k*OUTD + tid];
        out[(size_t)b*OUTD + tid] = v;
    }
}

// ---------------- launcher ----------------
extern "C" void kernel_launch(void* const* d_in, const int* in_sizes, int n_in,
                              void* d_out, int out_size) {
    const float* nodes = (const float*)d_in[0];
    const float* edges = (const float*)d_in[1];
    const float* W_msg = (const float*)d_in[2];
    const float* W_ih  = (const float*)d_in[3];
    const float* W_hh  = (const float*)d_in[4];
    const float* b_ih  = (const float*)d_in[5];
    const float* b_hh  = (const float*)d_in[6];
    const float* Wg    = (const float*)d_in[7];
    const float* bg    = (const float*)d_in[8];
    const float* We    = (const float*)d_in[9];
    const float* be    = (const float*)d_in[10];
    const float* Wo    = (const float*)d_in[11];
    const float* bo    = (const float*)d_in[12];
    float* out = (float*)d_out;

    prep_weights<<<(100000 + 255) / 256, 256>>>(W_msg, W_ih, W_hh);
    prep_edges<<<(NODES*32 + 255) / 256, 256>>>(edges);
    fused_kernel<<<BB, NTHR>>>(nodes, b_ih, b_hh, Wg, bg, We, be, Wo, bo, out);
}

// round 6
// speedup vs baseline: 1.7366x; 1.1625x over previous
#include <cuda_runtime.h>
#include <math.h>

#define BB    256
#define NN    32
#define FF    40
#define HH    100
#define MM    100
#define EFN   4
#define OUTD  128
#define H3    300
#define KMAX  8
#define NODES (BB*NN)   // 8192
#define TPAD  40        // T row stride (floats) -> 160B, 16B-aligned rows
#define STAGE (100*TPAD) // float offset of weight-staging region inside sh_T
#define NTHR  416

typedef unsigned long long ull;

// ---------------- device scratch ----------------
__device__ __align__(16) float g_Wm[EFN*HH*MM];    // [f][k][m]
__device__ __align__(16) float g_Wp[HH*HH*6];      // [k][h][6] = {WihR,WihZ,WihN,WhhR,WhhZ,WhhN}
__device__ __align__(16) float g_Wge[140*HH*2];    // [k][h][2] = {Wg, We(0 for k>=100)}
__device__ int   g_nbr[NODES*KMAX];
__device__ int   g_typ[NODES*KMAX];
__device__ float g_wgt[NODES*KMAX];
__device__ int   g_cnt[NODES];

__device__ __forceinline__ float sigmf(float x) { return 1.0f / (1.0f + expf(-x)); }
__device__ __forceinline__ ull packdup(float w) {
    ull r; asm("mov.b64 %0,{%1,%1};" : "=l"(r) : "f"(w)); return r;
}
__device__ __forceinline__ void unpack2(ull v, float& lo, float& hi) {
    asm("mov.b64 {%0,%1},%2;" : "=f"(lo), "=f"(hi) : "l"(v));
}
__device__ __forceinline__ void fma2(ull& d, ull a, ull b) {
    asm("fma.rn.f32x2 %0, %1, %2, %0;" : "+l"(d) : "l"(a), "l"(b));
}

// ---------------- prep: weight layouts ----------------
__global__ void prep_weights(const float* __restrict__ W_msg,
                             const float* __restrict__ W_ih,
                             const float* __restrict__ W_hh,
                             const float* __restrict__ Wg,
                             const float* __restrict__ We) {
    int gid = blockIdx.x * blockDim.x + threadIdx.x;
    const int NWT = EFN*HH*MM;            // 40000
    if (gid < NWT) {
        int f = gid / (HH*MM);
        int rem = gid % (HH*MM);
        int k = rem / MM;
        int m = rem % MM;
        g_Wm[gid] = W_msg[(m*HH + k)*EFN + f];
    } else if (gid < NWT + HH*HH) {       // 10000 (k,h) entries
        int t = gid - NWT;
        int k = t / HH, h = t % HH;
        float* dst = g_Wp + (size_t)t*6;
        dst[0] = W_ih[(h)*HH + k];
        dst[1] = W_ih[(100+h)*HH + k];
        dst[2] = W_ih[(200+h)*HH + k];
        dst[3] = W_hh[(h)*HH + k];
        dst[4] = W_hh[(100+h)*HH + k];
        dst[5] = W_hh[(200+h)*HH + k];
    } else if (gid < NWT + HH*HH + 140*HH) {
        int t = gid - NWT - HH*HH;
        int k = t / HH, h = t % HH;
        g_Wge[(size_t)t*2 + 0] = Wg[k*HH + h];
        g_Wge[(size_t)t*2 + 1] = (k < HH) ? We[k*HH + h] : 0.0f;
    }
}

// ---------------- prep: compact edge lists (warp per node) ----------------
__global__ void prep_edges(const float* __restrict__ edges) {
    int warp = (blockIdx.x * blockDim.x + threadIdx.x) >> 5;
    int lane = threadIdx.x & 31;
    if (warp >= NODES) return;
    int p = warp;
    float4 v = ((const float4*)edges)[(size_t)p * NN + lane];
    float vv[4] = {v.x, v.y, v.z, v.w};
    int nl = (vv[0]!=0.f) + (vv[1]!=0.f) + (vv[2]!=0.f) + (vv[3]!=0.f);
    int inc = nl;
    #pragma unroll
    for (int off = 1; off < 32; off <<= 1) {
        int t = __shfl_up_sync(0xFFFFFFFFu, inc, off);
        if (lane >= off) inc += t;
    }
    int excl = inc - nl;
    int total = __shfl_sync(0xFFFFFFFFu, inc, 31);
    int c = excl;
    #pragma unroll
    for (int f = 0; f < EFN; f++) {
        if (vv[f] != 0.f && c < KMAX) {
            g_nbr[p*KMAX + c] = lane;
            g_typ[p*KMAX + c] = f;
            g_wgt[p*KMAX + c] = vv[f];
            c++;
        }
    }
    if (lane == 0) g_cnt[p] = (total < KMAX) ? total : KMAX;
}

// ---------------- fused: 3 passes + readout, one block per batch ----------
__global__ __launch_bounds__(NTHR, 2) void fused_kernel(
        const float* __restrict__ nodes,
        const float* __restrict__ b_ih, const float* __restrict__ b_hh,
        const float* __restrict__ bg,   const float* __restrict__ be,
        const float* __restrict__ Wo,   const float* __restrict__ bo,
        float* __restrict__ out) {
    __shared__ __align__(16) float sh_h[HH*NN];          // [k][n] 12.8KB
    __shared__ __align__(16) float sh_T[EFN*HH*TPAD];    // 64KB: T / msg(f0 rows) / stage
    __shared__ int   sh_nbr[NN][KMAX];
    __shared__ int   sh_typ[NN][KMAX];
    __shared__ float sh_wgt[NN][KMAX];
    __shared__ int   sh_cnt[NN];
    __shared__ float sh_part[4*HH];
    __shared__ float sh_acc[HH];

    const int b   = blockIdx.x;
    const int tid = threadIdx.x;
    const int p0  = b * NN;

    // edge meta
    if (tid < NN) sh_cnt[tid] = g_cnt[p0 + tid];
    else if (tid >= 32 && tid < 32 + NN*KMAX) {
        int t = tid - 32; int n = t >> 3, e = t & 7;
        sh_nbr[n][e] = g_nbr[(p0+n)*KMAX + e];
        sh_typ[n][e] = g_typ[(p0+n)*KMAX + e];
        sh_wgt[n][e] = g_wgt[(p0+n)*KMAX + e];
    }
    // hidden init: [nodes | 0]
    for (int idx = tid; idx < HH*NN; idx += NTHR) {
        int k = idx >> 5, n = idx & 31;
        sh_h[idx] = (k < FF) ? nodes[(size_t)(p0+n)*FF + k] : 0.0f;
    }
    __syncthreads();

    const int hh = (tid < 400) ? (tid % 100) : 0;
    const int ng = (tid < 400) ? (tid / 100) : 0;

    for (int pass = 0; pass < 3; pass++) {
        // ---- T[f][m][n] = sum_k Wm[f][k][m] * h[k][n] ----
        if (tid < 400) {
            const int f = tid / 100, m = tid - f*100;
            ull acc[16];
            #pragma unroll
            for (int j = 0; j < 16; j++) acc[j] = 0ull;
            const float* W = g_Wm + (size_t)(f*HH)*MM + m;
            for (int k = 0; k < HH; k++) {
                ull w = packdup(W[k*MM]);
                const ulonglong2* hp = (const ulonglong2*)(sh_h + k*NN);
                ulonglong2 v0 = hp[0], v1 = hp[1], v2 = hp[2], v3 = hp[3];
                fma2(acc[0], w, v0.x); fma2(acc[1], w, v0.y);
                fma2(acc[2], w, v1.x); fma2(acc[3], w, v1.y);
                fma2(acc[4], w, v2.x); fma2(acc[5], w, v2.y);
                fma2(acc[6], w, v3.x); fma2(acc[7], w, v3.y);
                ulonglong2 v4 = hp[4], v5 = hp[5], v6 = hp[6], v7 = hp[7];
                fma2(acc[8],  w, v4.x); fma2(acc[9],  w, v4.y);
                fma2(acc[10], w, v5.x); fma2(acc[11], w, v5.y);
                fma2(acc[12], w, v6.x); fma2(acc[13], w, v6.y);
                fma2(acc[14], w, v7.x); fma2(acc[15], w, v7.y);
            }
            ulonglong2* Trow = (ulonglong2*)(sh_T + (size_t)(f*MM + m)*TPAD);
            #pragma unroll
            for (int j = 0; j < 8; j++) Trow[j] = make_ulonglong2(acc[2*j], acc[2*j+1]);
        }
        __syncthreads();

        // ---- gather to regs: msg[m][n] = sum_e w_e * T[f_e][m][g_e] ----
        float res[8];
        if (tid < 400) {
            const int m = tid >> 2;
            const int n0 = (tid & 3) * 8;
            #pragma unroll
            for (int j = 0; j < 8; j++) {
                int n = n0 + j;
                int c = sh_cnt[n];
                float s = 0.f;
                for (int e = 0; e < c; e++) {
                    s += sh_wgt[n][e] *
                         sh_T[(size_t)(sh_typ[n][e]*MM + m)*TPAD + sh_nbr[n][e]];
                }
                res[j] = s;
            }
        }
        __syncthreads();
        if (tid < 400) {   // write msg into T f=0 rows: sh_T[m*TPAD + n]
            const int m = tid >> 2;
            const int n0 = (tid & 3) * 8;
            float4* dst = (float4*)(sh_T + (size_t)m*TPAD + n0);
            dst[0] = make_float4(res[0], res[1], res[2], res[3]);
            dst[1] = make_float4(res[4], res[5], res[6], res[7]);
        }
        __syncthreads();

        // ---- GRU: thread (hh, ng) owns (h, 8 nodes); gates merged ----
        ull accA[4], accB[4], accC[4], accD[4];  // r-sum, z-sum, gi_n, gh_n
        #pragma unroll
        for (int j = 0; j < 4; j++) { accA[j]=0; accB[j]=0; accC[j]=0; accD[j]=0; }

        for (int t = 0; t < HH; t += 16) {
            const int kt = (HH - t < 16) ? (HH - t) : 16;
            __syncthreads();   // previous tile fully consumed
            {   // stage weights [kk][h][6] (coalesced, each byte once)
                const float4* src = (const float4*)(g_Wp + (size_t)t*600);
                float4* dst = (float4*)(sh_T + STAGE);
                for (int i = tid; i < kt*150; i += NTHR) dst[i] = src[i];
            }
            __syncthreads();
            if (tid < 400) {
                for (int kk = 0; kk < kt; kk++) {
                    const int k = t + kk;
                    const ull* wp = (const ull*)(sh_T + STAGE + kk*600 + hh*6);
                    ull w01 = wp[0], w23 = wp[1], w45 = wp[2];
                    float wir, wiz, win, whr, whz, whn;
                    unpack2(w01, wir, wiz);
                    unpack2(w23, win, whr);
                    unpack2(w45, whz, whn);
                    ull dIR = packdup(wir), dIZ = packdup(wiz), dIN = packdup(win);
                    ull dHR = packdup(whr), dHZ = packdup(whz), dHN = packdup(whn);
                    const ulonglong2* mp = (const ulonglong2*)(sh_T + (size_t)k*TPAD + ng*8);
                    const ulonglong2* hp = (const ulonglong2*)(sh_h + k*NN + ng*8);
                    ulonglong2 m01 = mp[0], m23 = mp[1];
                    ulonglong2 h01 = hp[0], h23 = hp[1];
                    fma2(accA[0], dIR, m01.x); fma2(accA[0], dHR, h01.x);
                    fma2(accA[1], dIR, m01.y); fma2(accA[1], dHR, h01.y);
                    fma2(accA[2], dIR, m23.x); fma2(accA[2], dHR, h23.x);
                    fma2(accA[3], dIR, m23.y); fma2(accA[3], dHR, h23.y);
                    fma2(accB[0], dIZ, m01.x); fma2(accB[0], dHZ, h01.x);
                    fma2(accB[1], dIZ, m01.y); fma2(accB[1], dHZ, h01.y);
                    fma2(accB[2], dIZ, m23.x); fma2(accB[2], dHZ, h23.x);
                    fma2(accB[3], dIZ, m23.y); fma2(accB[3], dHZ, h23.y);
                    fma2(accC[0], dIN, m01.x); fma2(accC[1], dIN, m01.y);
                    fma2(accC[2], dIN, m23.x); fma2(accC[3], dIN, m23.y);
                    fma2(accD[0], dHN, h01.x); fma2(accD[1], dHN, h01.y);
                    fma2(accD[2], dHN, h23.x); fma2(accD[3], dHN, h23.y);
                }
            }
        }

        // previous h values for this (h, 8 nodes)
        ull hv[4];
        if (tid < 400) {
            const ulonglong2* hvp = (const ulonglong2*)(sh_h + hh*NN + ng*8);
            ulonglong2 a = hvp[0], c = hvp[1];
            hv[0] = a.x; hv[1] = a.y; hv[2] = c.x; hv[3] = c.y;
        }
        __syncthreads();   // everyone done reading sh_h / sh_T(msg)

        if (tid < 400) {
            const float brz = b_ih[hh]       + b_hh[hh];
            const float bzz = b_ih[100 + hh] + b_hh[100 + hh];
            const float bin = b_ih[200 + hh];
            const float bhn = b_hh[200 + hh];
            float o[8];
            #pragma unroll
            for (int j = 0; j < 4; j++) {
                float a0, a1, zb0, zb1, c0, c1, d0, d1, h0, h1;
                unpack2(accA[j], a0, a1);
                unpack2(accB[j], zb0, zb1);
                unpack2(accC[j], c0, c1);
                unpack2(accD[j], d0, d1);
                unpack2(hv[j], h0, h1);
                int nA = ng*8 + 2*j, nB = nA + 1;
                {
                    float r = sigmf(a0 + brz);
                    float z = sigmf(zb0 + bzz);
                    float nv = tanhf(c0 + bin + r*(d0 + bhn));
                    o[2*j]   = (sh_cnt[nA] == 0) ? h0 : (1.0f - z)*nv + z*h0;
                }
                {
                    float r = sigmf(a1 + brz);
                    float z = sigmf(zb1 + bzz);
                    float nv = tanhf(c1 + bin + r*(d1 + bhn));
                    o[2*j+1] = (sh_cnt[nB] == 0) ? h1 : (1.0f - z)*nv + z*h1;
                }
            }
            float4* dst = (float4*)(sh_h + hh*NN + ng*8);
            dst[0] = make_float4(o[0], o[1], o[2], o[3]);
            dst[1] = make_float4(o[4], o[5], o[6], o[7]);
        }
        __syncthreads();
    }

    // ---- readout ----
    // stage x transposed into staging region: x[k][n]
    for (int idx = tid; idx < NN*FF; idx += NTHR) {
        int n = idx / FF, k = idx % FF;     // global-coalesced read
        sh_T[STAGE + k*NN + n] = nodes[(size_t)(p0+n)*FF + k];
    }
    __syncthreads();

    if (tid < 400) {
        ull ga[4], ev[4];
        #pragma unroll
        for (int j = 0; j < 4; j++) { ga[j] = 0; ev[j] = 0; }
        for (int k = 0; k < HH; k++) {
            ull wge = *(const ull*)(g_Wge + (size_t)(k*HH + hh)*2);
            float wg, we; unpack2(wge, wg, we);
            ull dwg = packdup(wg), dwe = packdup(we);
            const ulonglong2* hp = (const ulonglong2*)(sh_h + k*NN + ng*8);
            ulonglong2 a = hp[0], c = hp[1];
            fma2(ga[0], dwg, a.x); fma2(ga[1], dwg, a.y);
            fma2(ga[2], dwg, c.x); fma2(ga[3], dwg, c.y);
            fma2(ev[0], dwe, a.x); fma2(ev[1], dwe, a.y);
            fma2(ev[2], dwe, c.x); fma2(ev[3], dwe, c.y);
        }
        for (int k = 0; k < FF; k++) {
            ull dwg = packdup(g_Wge[(size_t)((HH + k)*HH + hh)*2]);
            const ulonglong2* xp = (const ulonglong2*)(sh_T + STAGE + k*NN + ng*8);
            ulonglong2 a = xp[0], c = xp[1];
            fma2(ga[0], dwg, a.x); fma2(ga[1], dwg, a.y);
            fma2(ga[2], dwg, c.x); fma2(ga[3], dwg, c.y);
        }
        float bgv = bg[hh], bev = be[hh];
        float s = 0.f;
        #pragma unroll
        for (int j = 0; j < 4; j++) {
            float gl, gh_, el, eh;
            unpack2(ga[j], gl, gh_);
            unpack2(ev[j], el, eh);
            int nA = ng*8 + 2*j, nB = nA + 1;
            if (sh_cnt[nA] != 0) s += sigmf(gl + bgv) * (el + bev);
            if (sh_cnt[nB] != 0) s += sigmf(gh_ + bgv) * (eh + bev);
        }
        sh_part[ng*HH + hh] = s;
    }
    __syncthreads();
    if (tid < HH)
        sh_acc[tid] = sh_part[tid] + sh_part[HH + tid] + sh_part[2*HH + tid] + sh_part[3*HH + tid];
    __syncthreads();

    if (tid < OUTD) {
        float v = bo[tid];
        #pragma unroll 4
        for (int k = 0; k < HH; k++) v += sh_acc[k] * Wo[k*OUTD + tid];
        out[(size_t)b*OUTD + tid] = v;
    }
}

// ---------------- launcher ----------------
extern "C" void kernel_launch(void* const* d_in, const int* in_sizes, int n_in,
                              void* d_out, int out_size) {
    const float* nodes = (const float*)d_in[0];
    const float* edges = (const float*)d_in[1];
    const float* W_msg = (const float*)d_in[2];
    const float* W_ih  = (const float*)d_in[3];
    const float* W_hh  = (const float*)d_in[4];
    const float* b_ih  = (const float*)d_in[5];
    const float* b_hh  = (const float*)d_in[6];
    const float* Wg    = (const float*)d_in[7];
    const float* bg    = (const float*)d_in[8];
    const float* We    = (const float*)d_in[9];
    const float* be    = (const float*)d_in[10];
    const float* Wo    = (const float*)d_in[11];
    const float* bo    = (const float*)d_in[12];
    float* out = (float*)d_out;

    prep_weights<<<(64000 + 255) / 256, 256>>>(W_msg, W_ih, W_hh, Wg, We);
    prep_edges<<<(NODES*32 + 255) / 256, 256>>>(edges);
    fused_kernel<<<BB, NTHR>>>(nodes, b_ih, b_hh, bg, be, Wo, bo, out);
}